// round 16
// baseline (speedup 1.0000x reference)
#include <cuda_runtime.h>
#include <cuda_fp16.h>
#include <mma.h>
#include <math.h>
#include <stdint.h>

using namespace nvcuda;

#define D_   768
#define H_   12
#define HD_  64
#define WSZ  128
#define B_   4
#define L_   8190
#define LP_  8192
#define NTOK (B_*LP_)   /* 32768 */

// Scratch
__device__ __half g_x[(size_t)NTOK * D_];    // fp16, zero-padded input
__device__ __half g_wt[4 * 589824];          // fp16, TRANSPOSED weights: [z*768+n][k]
__device__ float  g_bias[4 * D_];            // concat bq,bk,bv,bo
__device__ __half g_q[(size_t)NTOK * D_];
__device__ __half g_k[(size_t)NTOK * D_];
__device__ __half g_v[(size_t)NTOK * D_];
__device__ __half g_o[(size_t)NTOK * D_];
__device__ float  g_y[(size_t)NTOK * D_];

__device__ __forceinline__ void cpa16(uint32_t s, const void* g) {
    asm volatile("cp.async.cg.shared.global [%0], [%1], 16;" :: "r"(s), "l"(g));
}
template<int N> __device__ __forceinline__ void cp_wait() {
    asm volatile("cp.async.wait_group %0;" :: "n"(N));
}
__device__ __forceinline__ void cp_commit() {
    asm volatile("cp.async.commit_group;");
}
__device__ __forceinline__ uint32_t smem_u32(const void* p) {
    uint32_t a;
    asm("{ .reg .u64 t; cvta.to.shared.u64 t, %1; cvt.u32.u64 %0, t; }" : "=r"(a) : "l"(p));
    return a;
}

extern __shared__ __align__(1024) float dynsm[];

// ---------------------------------------------------------------------------
// Prep kernels
// ---------------------------------------------------------------------------
__global__ __launch_bounds__(256) void prep_x(const float* __restrict__ X)
{
    size_t cidx = (size_t)blockIdx.x * 256 + threadIdx.x;   // 3145728 chunks of 8
    int tok = (int)(cidx / 96);
    int c8  = (int)(cidx - (size_t)tok * 96) * 8;
    int b = tok >> 13;
    int l = tok & (LP_ - 1);
    float4 v0 = make_float4(0.f, 0.f, 0.f, 0.f);
    float4 v1 = make_float4(0.f, 0.f, 0.f, 0.f);
    if (l < L_) {
        const float* src = X + (size_t)(b * L_ + l) * D_ + c8;
        v0 = *(const float4*)(src);
        v1 = *(const float4*)(src + 4);
    }
    __half2 h[4];
    h[0] = __floats2half2_rn(v0.x, v0.y);
    h[1] = __floats2half2_rn(v0.z, v0.w);
    h[2] = __floats2half2_rn(v1.x, v1.y);
    h[3] = __floats2half2_rn(v1.z, v1.w);
    *(uint4*)(g_x + cidx * 8) = *(uint4*)h;
}

__global__ __launch_bounds__(256) void prep_wt(
    const float* __restrict__ Wq, const float* __restrict__ Wk,
    const float* __restrict__ Wv, const float* __restrict__ Wo)
{
    __shared__ float t[32][33];
    const int z = blockIdx.z;
    const float* W = (z == 0) ? Wq : (z == 1) ? Wk : (z == 2) ? Wv : Wo;
    const int k0 = blockIdx.x * 32;
    const int n0 = blockIdx.y * 32;
    const int tx = threadIdx.x & 31;
    const int ty = threadIdx.x >> 5;      // 0..7
#pragma unroll
    for (int i = 0; i < 4; i++)
        t[ty + 8 * i][tx] = W[(size_t)(k0 + ty + 8 * i) * D_ + n0 + tx];
    __syncthreads();
#pragma unroll
    for (int i = 0; i < 4; i++)
        g_wt[(size_t)(z * D_ + n0 + ty + 8 * i) * D_ + k0 + tx] = __float2half_rn(t[tx][ty + 8 * i]);
}

__global__ __launch_bounds__(256) void prep_bias(
    const float* __restrict__ bq, const float* __restrict__ bk,
    const float* __restrict__ bv, const float* __restrict__ bo)
{
    int idx = blockIdx.x * 256 + threadIdx.x;   // 3072
    int z = idx / D_, j = idx - z * D_;
    const float* s = (z == 0) ? bq : (z == 1) ? bk : (z == 2) ? bv : bo;
    g_bias[idx] = s[j];
}

// ---------------------------------------------------------------------------
// fp16 GEMM: 256 threads, CTA 128(M) x 128(N), warp tile 64x32 (2x4 warps),
// K-chunk 64, THREE-stage cp.async pipeline, one sync per K-iter, 2 CTAs/SM.
// (unchanged from round-15 best)
// ---------------------------------------------------------------------------
#define AST 72                       /* halves: 64 + 8 pad (row = 144B) */
#define A_BUFH (128 * AST)           /* 9216 halves */
#define B_BUFH (128 * AST)
#define STAGEH (A_BUFH + B_BUFH)     /* 18432 halves = 36864 B */
#define GEMM_SMEM (3 * STAGEH * 2)   /* 110592 B; 2 CTAs/SM */

typedef wmma::fragment<wmma::matrix_a, 16, 16, 16, __half, wmma::row_major> HFragA;
typedef wmma::fragment<wmma::matrix_b, 16, 16, 16, __half, wmma::row_major> HFragB;
typedef wmma::fragment<wmma::matrix_b, 16, 16, 16, __half, wmma::col_major> HFragBc;
typedef wmma::fragment<wmma::accumulator, 16, 16, 16, float> HFragC;

__device__ __forceinline__ void ld_stage(const __half* Ap, const __half* Bp,
                                         uint32_t smb, int tid, int m0, int wrow0, int jt)
{
    const uint32_t sb = smb + (jt % 3) * (STAGEH * 2);
    const int k0 = jt * 64;
#pragma unroll
    for (int i = 0; i < 4; i++) {                 // A: 1024 chunks of 8 halves
        int idx = tid + i * 256;
        int r = idx >> 3, c = (idx & 7) << 3;
        cpa16(sb + (r * AST + c) * 2, Ap + (size_t)(m0 + r) * D_ + k0 + c);
    }
#pragma unroll
    for (int i = 0; i < 4; i++) {                 // B: 1024 chunks
        int idx = tid + i * 256;
        int r = idx >> 3, c = (idx & 7) << 3;
        cpa16(sb + (A_BUFH * 2) + (r * AST + c) * 2, Bp + (size_t)(wrow0 + r) * D_ + k0 + c);
    }
    cp_commit();
}

template <int MODE>
__global__ __launch_bounds__(256, 2) void gemm_kernel(const float* __restrict__ X)
{
    const uint32_t smb = smem_u32(dynsm);
    const int m0 = blockIdx.x * 128;
    const int ytile = blockIdx.y;
    const int wrow0 = (MODE == 0) ? ytile * 128 : 2304 + ytile * 128;
    const __half* Ap = (MODE == 0) ? g_x : g_o;

    const int tid = threadIdx.x;
    const int wid = tid >> 5;
    const int wm = wid >> 2;     // 0..1 (64-row strips)
    const int wn = wid & 3;      // 0..3 (32-col strips)

    HFragC acc[4][2];
#pragma unroll
    for (int i = 0; i < 4; i++)
#pragma unroll
        for (int j = 0; j < 2; j++) wmma::fill_fragment(acc[i][j], 0.0f);

    ld_stage(Ap, g_wt, smb, tid, m0, wrow0, 0);
    ld_stage(Ap, g_wt, smb, tid, m0, wrow0, 1);

    for (int it = 0; it < 12; it++) {
        if (it < 11) cp_wait<1>(); else cp_wait<0>();
        __syncthreads();
        if (it < 10) ld_stage(Ap, g_wt, smb, tid, m0, wrow0, it + 2);

        const __half* Ab = (const __half*)dynsm + (it % 3) * STAGEH;
        const __half* Bb = Ab + A_BUFH;
#pragma unroll
        for (int ks = 0; ks < 4; ks++) {
            HFragA a[4];
            HFragBc b[2];
#pragma unroll
            for (int i = 0; i < 4; i++)
                wmma::load_matrix_sync(a[i], Ab + (wm * 64 + i * 16) * AST + ks * 16, AST);
#pragma unroll
            for (int j = 0; j < 2; j++)
                wmma::load_matrix_sync(b[j], Bb + (wn * 32 + j * 16) * AST + ks * 16, AST);
#pragma unroll
            for (int i = 0; i < 4; i++)
#pragma unroll
                for (int j = 0; j < 2; j++)
                    wmma::mma_sync(acc[i][j], a[i], b[j], acc[i][j]);
        }
    }

    // Epilogue in two 64-row halves via fp32 smem staging [64][132]
    float* St = dynsm;
#pragma unroll
    for (int half = 0; half < 2; half++) {
        if (wm == half) {
#pragma unroll
            for (int i = 0; i < 4; i++)
#pragma unroll
                for (int j = 0; j < 2; j++)
                    wmma::store_matrix_sync(St + (i * 16) * 132 + wn * 32 + j * 16,
                                            acc[i][j], 132, wmma::mem_row_major);
        }
        __syncthreads();

        if (MODE == 0) {
            const int z = ytile / 6;
            const int n0 = (ytile % 6) * 128;
            const float* bb = g_bias + ytile * 128;
            __half* Out = (z == 0) ? g_q : (z == 1) ? g_k : g_v;
#pragma unroll
            for (int i = 0; i < 8; i++) {
                int idx = tid + i * 256;
                int r = idx >> 5, c4 = (idx & 31) << 2;
                float4 v = *(const float4*)(St + r * 132 + c4);
                const float4 bv = *(const float4*)(bb + c4);
                __half2 h0 = __floats2half2_rn(v.x + bv.x, v.y + bv.y);
                __half2 h1 = __floats2half2_rn(v.z + bv.z, v.w + bv.w);
                uint2 pk = make_uint2(*(uint32_t*)&h0, *(uint32_t*)&h1);
                *(uint2*)(Out + (size_t)(m0 + half * 64 + r) * D_ + n0 + c4) = pk;
            }
        } else {
            const int n0 = ytile * 128;
            const float* bb = g_bias + 2304 + n0;
#pragma unroll
            for (int i = 0; i < 8; i++) {
                int idx = tid + i * 256;
                int r = idx >> 5, c4 = (idx & 31) << 2;
                float4 v = *(const float4*)(St + r * 132 + c4);
                const float4 bv = *(const float4*)(bb + c4);
                int tok = m0 + half * 64 + r;
                int b = tok >> 13;
                int l = tok & (LP_ - 1);
                float4 res = make_float4(0.f, 0.f, 0.f, 0.f);
                if (l < L_) res = *(const float4*)(X + (size_t)(b * L_ + l) * D_ + n0 + c4);
                v.x += bv.x + res.x;
                v.y += bv.y + res.y;
                v.z += bv.z + res.z;
                v.w += bv.w + res.w;
                *(float4*)(g_y + (size_t)tok * D_ + n0 + c4) = v;
            }
        }
        __syncthreads();
    }
}

// ---------------------------------------------------------------------------
// Attention per (head, window), 256 threads, FOUR passes over 32 query rows.
// smem: Q[32][72]h | K[128][72]h | V[128][72]h | S[32][132]f | P[32][136]h
//       4608       | 18432       | 18432       | 16896       | 8704 = 67072 B
// 3 CTAs/SM (201 KB). Softmax without max-shift (fp32-safe here).
// ---------------------------------------------------------------------------
#define QKVS 72
#define SST  132
#define PST  136
#define ATTN_SMEM 67072

__global__ __launch_bounds__(256, 3) void attn_kernel()
{
    __half* Q = (__half*)dynsm;                       // [32][72]
    __half* K = (__half*)((char*)dynsm + 4608);       // [128][72]
    __half* V = (__half*)((char*)dynsm + 23040);      // [128][72]
    float*  S = (float*)((char*)dynsm + 41472);       // [32][132]
    __half* P = (__half*)((char*)dynsm + 58368);      // [32][136]

    const int h = blockIdx.x;
    const int tok0 = blockIdx.y * 128;
    const int tid = threadIdx.x;
    const int wid = tid >> 5;
    const int wm = wid >> 2;                  // 0..1 (16-row strips)
    const int wn = wid & 3;                   // 0..3

    const uint32_t smb = smem_u32(dynsm);

    // load K,V full window via cp.async: 128x64 halves each
#pragma unroll
    for (int it = 0; it < 4; it++) {
        int idx = tid + it * 256;             // 0..1023
        int r = idx >> 3;
        int c8 = (idx & 7) * 8;
        size_t g = (size_t)(tok0 + r) * D_ + h * HD_ + c8;
        cpa16(smb + 4608 + (r * QKVS + c8) * 2, g_k + g);
        cpa16(smb + 23040 + (r * QKVS + c8) * 2, g_v + g);
    }
    cp_commit();
    cp_wait<0>();

#pragma unroll
    for (int p = 0; p < 4; p++) {
        const int q0 = tok0 + p * 32;
        // load Q: 32x64 halves (256 uint4 chunks, 1 per thread)
        {
            int r = tid >> 3;
            int c8 = (tid & 7) * 8;
            *(uint4*)(Q + r * QKVS + c8) = *(const uint4*)(g_q + (size_t)(q0 + r) * D_ + h * HD_ + c8);
        }
        __syncthreads();

        // S = Q @ K^T : each warp 16(rows) x 64(cols), 4 k-steps
        {
            HFragC acc[2];
#pragma unroll
            for (int j = 0; j < 2; j++) wmma::fill_fragment(acc[j], 0.0f);
#pragma unroll
            for (int kk = 0; kk < 4; kk++) {
                HFragA a0;
                wmma::load_matrix_sync(a0, Q + (wm * 16) * QKVS + kk * 16, QKVS);
#pragma unroll
                for (int j = 0; j < 2; j++) {
                    HFragBc bf;
                    wmma::load_matrix_sync(bf, K + (wn * 32 + j * 16) * QKVS + kk * 16, QKVS);
                    wmma::mma_sync(acc[j], a0, bf, acc[j]);
                }
            }
#pragma unroll
            for (int j = 0; j < 2; j++)
                wmma::store_matrix_sync(S + (wm * 16) * SST + wn * 32 + j * 16,
                                        acc[j], SST, wmma::mem_row_major);
        }
        __syncthreads();

        // softmax: 8 threads per row, 16 cols each; no max-shift; P -> fp16
        {
            const int row = tid >> 3;         // 0..31
            const int qu  = tid & 7;
            float4* seg = (float4*)(S + row * SST + qu * 16);
            __half2* pr = (__half2*)(P + row * PST + qu * 16);
            const float scale = 0.125f;
            float sum = 0.0f;
            float4 e[4];
#pragma unroll
            for (int j = 0; j < 4; j++) {
                float4 v = seg[j];
                v.x = __expf(v.x * scale);
                v.y = __expf(v.y * scale);
                v.z = __expf(v.z * scale);
                v.w = __expf(v.w * scale);
                sum += v.x + v.y + v.z + v.w;
                e[j] = v;
            }
            sum += __shfl_xor_sync(0xffffffffu, sum, 1);
            sum += __shfl_xor_sync(0xffffffffu, sum, 2);
            sum += __shfl_xor_sync(0xffffffffu, sum, 4);
            float inv = 1.0f / sum;
#pragma unroll
            for (int j = 0; j < 4; j++) {
                pr[j * 2]     = __floats2half2_rn(e[j].x * inv, e[j].y * inv);
                pr[j * 2 + 1] = __floats2half2_rn(e[j].z * inv, e[j].w * inv);
            }
        }
        __syncthreads();

        // O = P @ V : each warp 16(rows) x 16(cols), 8 k-steps; stage into S
        {
            HFragC acc;
            wmma::fill_fragment(acc, 0.0f);
#pragma unroll
            for (int kk = 0; kk < 8; kk++) {
                HFragA a0;
                HFragB bf;
                wmma::load_matrix_sync(a0, P + (wm * 16) * PST + kk * 16, PST);
                wmma::load_matrix_sync(bf, V + (kk * 16) * QKVS + wn * 16, QKVS);
                wmma::mma_sync(acc, a0, bf, acc);
            }
            wmma::store_matrix_sync(S + (wm * 16) * SST + wn * 16, acc, SST,
                                    wmma::mem_row_major);
        }
        __syncthreads();

        // convert-write O: 32x64 halves (512 uint2 chunks, 2 per thread)
#pragma unroll
        for (int it = 0; it < 2; it++) {
            int idx = tid + it * 256;         // 0..511
            int r = idx >> 4;
            int c4 = (idx & 15) * 4;
            float4 v = *(const float4*)(S + r * SST + c4);
            __half2 h0 = __floats2half2_rn(v.x, v.y);
            __half2 h1 = __floats2half2_rn(v.z, v.w);
            uint2 pk = make_uint2(*(uint32_t*)&h0, *(uint32_t*)&h1);
            *(uint2*)(g_o + (size_t)(q0 + r) * D_ + h * HD_ + c4) = pk;
        }
        __syncthreads();   // S/Q reuse next pass
    }
}

// ---------------------------------------------------------------------------
// LayerNorm: 192 threads, one float4 per thread.
// ---------------------------------------------------------------------------
__global__ __launch_bounds__(192) void ln_kernel(
    const float* __restrict__ gam, const float* __restrict__ bet,
    float* __restrict__ out)
{
    const int t = blockIdx.x;
    const int b = t / L_;
    const int l = t - b * L_;
    const float4* y = (const float4*)(g_y + (size_t)(b * LP_ + l) * D_);
    const int tid = threadIdx.x;

    float4 v = y[tid];
    float s  = v.x + v.y + v.z + v.w;
    float ss = v.x * v.x + v.y * v.y + v.z * v.z + v.w * v.w;

    __shared__ float red_s[6], red_q[6];
#pragma unroll
    for (int off = 16; off > 0; off >>= 1) {
        s  += __shfl_down_sync(0xffffffffu, s, off);
        ss += __shfl_down_sync(0xffffffffu, ss, off);
    }
    if ((tid & 31) == 0) { red_s[tid >> 5] = s; red_q[tid >> 5] = ss; }
    __syncthreads();
    if (tid < 32) {
        float a = (tid < 6) ? red_s[tid] : 0.0f;
        float q = (tid < 6) ? red_q[tid] : 0.0f;
#pragma unroll
        for (int off = 4; off > 0; off >>= 1) {
            a += __shfl_down_sync(0xffffffffu, a, off);
            q += __shfl_down_sync(0xffffffffu, q, off);
        }
        if (tid == 0) { red_s[0] = a; red_q[0] = q; }
    }
    __syncthreads();

    float mu  = red_s[0] * (1.0f / D_);
    float var = red_q[0] * (1.0f / D_) - mu * mu;
    float inv = rsqrtf(var + 1e-5f);

    float4 g  = ((const float4*)gam)[tid];
    float4 be = ((const float4*)bet)[tid];
    float4 o;
    o.x = (v.x - mu) * inv * g.x + be.x;
    o.y = (v.y - mu) * inv * g.y + be.y;
    o.z = (v.z - mu) * inv * g.z + be.z;
    o.w = (v.w - mu) * inv * g.w + be.w;
    ((float4*)(out + (size_t)t * D_))[tid] = o;
}

// ---------------------------------------------------------------------------
extern "C" void kernel_launch(void* const* d_in, const int* in_sizes, int n_in,
                              void* d_out, int out_size)
{
    const float* x    = (const float*)d_in[0];
    const float* Wq   = (const float*)d_in[1];
    const float* bq   = (const float*)d_in[2];
    const float* Wk   = (const float*)d_in[3];
    const float* bk   = (const float*)d_in[4];
    const float* Wv   = (const float*)d_in[5];
    const float* bv   = (const float*)d_in[6];
    const float* Wo   = (const float*)d_in[7];
    const float* bo   = (const float*)d_in[8];
    const float* ln_g = (const float*)d_in[9];
    const float* ln_b = (const float*)d_in[10];
    float* out = (float*)d_out;

    cudaFuncSetAttribute(gemm_kernel<0>, cudaFuncAttributeMaxDynamicSharedMemorySize, GEMM_SMEM);
    cudaFuncSetAttribute(gemm_kernel<1>, cudaFuncAttributeMaxDynamicSharedMemorySize, GEMM_SMEM);
    cudaFuncSetAttribute(attn_kernel, cudaFuncAttributeMaxDynamicSharedMemorySize, ATTN_SMEM);

    prep_x<<<12288, 256>>>(x);
    prep_wt<<<dim3(24, 24, 4), 256>>>(Wq, Wk, Wv, Wo);
    prep_bias<<<12, 256>>>(bq, bk, bv, bo);
    gemm_kernel<0><<<dim3(NTOK / 128, 18), 256, GEMM_SMEM>>>(nullptr);
    attn_kernel<<<dim3(H_, NTOK / WSZ), 256, ATTN_SMEM>>>();
    gemm_kernel<1><<<dim3(NTOK / 128, 6), 256, GEMM_SMEM>>>(x);
    ln_kernel<<<B_ * L_, 192>>>(ln_g, ln_b, out);
}

// round 17
// speedup vs baseline: 1.0533x; 1.0533x over previous
#include <cuda_runtime.h>
#include <cuda_fp16.h>
#include <mma.h>
#include <math.h>
#include <stdint.h>

using namespace nvcuda;

#define D_   768
#define H_   12
#define HD_  64
#define WSZ  128
#define B_   4
#define L_   8190
#define LP_  8192
#define NTOK (B_*LP_)   /* 32768 */

// Scratch
__device__ __half g_x[(size_t)NTOK * D_];    // fp16, zero-padded input
__device__ __half g_wt[4 * 589824];          // fp16, TRANSPOSED weights: [z*768+n][k]
__device__ float  g_bias[4 * D_];            // concat bq,bk,bv,bo
__device__ __half g_q[(size_t)NTOK * D_];
__device__ __half g_k[(size_t)NTOK * D_];
__device__ __half g_v[(size_t)NTOK * D_];
__device__ __half g_o[(size_t)NTOK * D_];
__device__ float  g_y[(size_t)NTOK * D_];

__device__ __forceinline__ void cpa16(uint32_t s, const void* g) {
    asm volatile("cp.async.cg.shared.global [%0], [%1], 16;" :: "r"(s), "l"(g));
}
template<int N> __device__ __forceinline__ void cp_wait() {
    asm volatile("cp.async.wait_group %0;" :: "n"(N));
}
__device__ __forceinline__ void cp_commit() {
    asm volatile("cp.async.commit_group;");
}
__device__ __forceinline__ uint32_t smem_u32(const void* p) {
    uint32_t a;
    asm("{ .reg .u64 t; cvta.to.shared.u64 t, %1; cvt.u32.u64 %0, t; }" : "=r"(a) : "l"(p));
    return a;
}
__device__ __forceinline__ void mma16816(float* d, uint32_t a0, uint32_t a1,
                                         uint32_t a2, uint32_t a3,
                                         uint32_t b0, uint32_t b1) {
    asm volatile(
        "mma.sync.aligned.m16n8k16.row.col.f32.f16.f16.f32 "
        "{%0,%1,%2,%3}, {%4,%5,%6,%7}, {%8,%9}, {%0,%1,%2,%3};"
        : "+f"(d[0]), "+f"(d[1]), "+f"(d[2]), "+f"(d[3])
        : "r"(a0), "r"(a1), "r"(a2), "r"(a3), "r"(b0), "r"(b1));
}

extern __shared__ __align__(1024) float dynsm[];

// ---------------------------------------------------------------------------
// Prep kernels
// ---------------------------------------------------------------------------
__global__ __launch_bounds__(256) void prep_x(const float* __restrict__ X)
{
    size_t cidx = (size_t)blockIdx.x * 256 + threadIdx.x;   // 3145728 chunks of 8
    int tok = (int)(cidx / 96);
    int c8  = (int)(cidx - (size_t)tok * 96) * 8;
    int b = tok >> 13;
    int l = tok & (LP_ - 1);
    float4 v0 = make_float4(0.f, 0.f, 0.f, 0.f);
    float4 v1 = make_float4(0.f, 0.f, 0.f, 0.f);
    if (l < L_) {
        const float* src = X + (size_t)(b * L_ + l) * D_ + c8;
        v0 = *(const float4*)(src);
        v1 = *(const float4*)(src + 4);
    }
    __half2 h[4];
    h[0] = __floats2half2_rn(v0.x, v0.y);
    h[1] = __floats2half2_rn(v0.z, v0.w);
    h[2] = __floats2half2_rn(v1.x, v1.y);
    h[3] = __floats2half2_rn(v1.z, v1.w);
    *(uint4*)(g_x + cidx * 8) = *(uint4*)h;
}

__global__ __launch_bounds__(256) void prep_wt(
    const float* __restrict__ Wq, const float* __restrict__ Wk,
    const float* __restrict__ Wv, const float* __restrict__ Wo)
{
    __shared__ float t[32][33];
    const int z = blockIdx.z;
    const float* W = (z == 0) ? Wq : (z == 1) ? Wk : (z == 2) ? Wv : Wo;
    const int k0 = blockIdx.x * 32;
    const int n0 = blockIdx.y * 32;
    const int tx = threadIdx.x & 31;
    const int ty = threadIdx.x >> 5;      // 0..7
#pragma unroll
    for (int i = 0; i < 4; i++)
        t[ty + 8 * i][tx] = W[(size_t)(k0 + ty + 8 * i) * D_ + n0 + tx];
    __syncthreads();
#pragma unroll
    for (int i = 0; i < 4; i++)
        g_wt[(size_t)(z * D_ + n0 + ty + 8 * i) * D_ + k0 + tx] = __float2half_rn(t[tx][ty + 8 * i]);
}

__global__ __launch_bounds__(256) void prep_bias(
    const float* __restrict__ bq, const float* __restrict__ bk,
    const float* __restrict__ bv, const float* __restrict__ bo)
{
    int idx = blockIdx.x * 256 + threadIdx.x;   // 3072
    int z = idx / D_, j = idx - z * D_;
    const float* s = (z == 0) ? bq : (z == 1) ? bk : (z == 2) ? bv : bo;
    g_bias[idx] = s[j];
}

// ---------------------------------------------------------------------------
// fp16 GEMM: 256 threads, CTA 128(M) x 128(N), warp tile 64x32 (2x4 warps),
// K-chunk 64, THREE-stage cp.async pipeline, one sync per K-iter, 2 CTAs/SM.
// (unchanged from round-15 best)
// ---------------------------------------------------------------------------
#define AST 72                       /* halves: 64 + 8 pad (row = 144B) */
#define A_BUFH (128 * AST)           /* 9216 halves */
#define B_BUFH (128 * AST)
#define STAGEH (A_BUFH + B_BUFH)     /* 18432 halves = 36864 B */
#define GEMM_SMEM (3 * STAGEH * 2)   /* 110592 B; 2 CTAs/SM */

typedef wmma::fragment<wmma::matrix_a, 16, 16, 16, __half, wmma::row_major> HFragA;
typedef wmma::fragment<wmma::matrix_b, 16, 16, 16, __half, wmma::col_major> HFragBc;
typedef wmma::fragment<wmma::accumulator, 16, 16, 16, float> HFragC;

__device__ __forceinline__ void ld_stage(const __half* Ap, const __half* Bp,
                                         uint32_t smb, int tid, int m0, int wrow0, int jt)
{
    const uint32_t sb = smb + (jt % 3) * (STAGEH * 2);
    const int k0 = jt * 64;
#pragma unroll
    for (int i = 0; i < 4; i++) {                 // A: 1024 chunks of 8 halves
        int idx = tid + i * 256;
        int r = idx >> 3, c = (idx & 7) << 3;
        cpa16(sb + (r * AST + c) * 2, Ap + (size_t)(m0 + r) * D_ + k0 + c);
    }
#pragma unroll
    for (int i = 0; i < 4; i++) {                 // B: 1024 chunks
        int idx = tid + i * 256;
        int r = idx >> 3, c = (idx & 7) << 3;
        cpa16(sb + (A_BUFH * 2) + (r * AST + c) * 2, Bp + (size_t)(wrow0 + r) * D_ + k0 + c);
    }
    cp_commit();
}

template <int MODE>
__global__ __launch_bounds__(256, 2) void gemm_kernel(const float* __restrict__ X)
{
    const uint32_t smb = smem_u32(dynsm);
    const int m0 = blockIdx.x * 128;
    const int ytile = blockIdx.y;
    const int wrow0 = (MODE == 0) ? ytile * 128 : 2304 + ytile * 128;
    const __half* Ap = (MODE == 0) ? g_x : g_o;

    const int tid = threadIdx.x;
    const int wid = tid >> 5;
    const int wm = wid >> 2;     // 0..1 (64-row strips)
    const int wn = wid & 3;      // 0..3 (32-col strips)

    HFragC acc[4][2];
#pragma unroll
    for (int i = 0; i < 4; i++)
#pragma unroll
        for (int j = 0; j < 2; j++) wmma::fill_fragment(acc[i][j], 0.0f);

    ld_stage(Ap, g_wt, smb, tid, m0, wrow0, 0);
    ld_stage(Ap, g_wt, smb, tid, m0, wrow0, 1);

    for (int it = 0; it < 12; it++) {
        if (it < 11) cp_wait<1>(); else cp_wait<0>();
        __syncthreads();
        if (it < 10) ld_stage(Ap, g_wt, smb, tid, m0, wrow0, it + 2);

        const __half* Ab = (const __half*)dynsm + (it % 3) * STAGEH;
        const __half* Bb = Ab + A_BUFH;
#pragma unroll
        for (int ks = 0; ks < 4; ks++) {
            HFragA a[4];
            HFragBc b[2];
#pragma unroll
            for (int i = 0; i < 4; i++)
                wmma::load_matrix_sync(a[i], Ab + (wm * 64 + i * 16) * AST + ks * 16, AST);
#pragma unroll
            for (int j = 0; j < 2; j++)
                wmma::load_matrix_sync(b[j], Bb + (wn * 32 + j * 16) * AST + ks * 16, AST);
#pragma unroll
            for (int i = 0; i < 4; i++)
#pragma unroll
                for (int j = 0; j < 2; j++)
                    wmma::mma_sync(acc[i][j], a[i], b[j], acc[i][j]);
        }
    }

    // Epilogue in two 64-row halves via fp32 smem staging [64][132]
    float* St = dynsm;
#pragma unroll
    for (int half = 0; half < 2; half++) {
        if (wm == half) {
#pragma unroll
            for (int i = 0; i < 4; i++)
#pragma unroll
                for (int j = 0; j < 2; j++)
                    wmma::store_matrix_sync(St + (i * 16) * 132 + wn * 32 + j * 16,
                                            acc[i][j], 132, wmma::mem_row_major);
        }
        __syncthreads();

        if (MODE == 0) {
            const int z = ytile / 6;
            const int n0 = (ytile % 6) * 128;
            const float* bb = g_bias + ytile * 128;
            __half* Out = (z == 0) ? g_q : (z == 1) ? g_k : g_v;
#pragma unroll
            for (int i = 0; i < 8; i++) {
                int idx = tid + i * 256;
                int r = idx >> 5, c4 = (idx & 31) << 2;
                float4 v = *(const float4*)(St + r * 132 + c4);
                const float4 bv = *(const float4*)(bb + c4);
                __half2 h0 = __floats2half2_rn(v.x + bv.x, v.y + bv.y);
                __half2 h1 = __floats2half2_rn(v.z + bv.z, v.w + bv.w);
                uint2 pk = make_uint2(*(uint32_t*)&h0, *(uint32_t*)&h1);
                *(uint2*)(Out + (size_t)(m0 + half * 64 + r) * D_ + n0 + c4) = pk;
            }
        } else {
            const int n0 = ytile * 128;
            const float* bb = g_bias + 2304 + n0;
#pragma unroll
            for (int i = 0; i < 8; i++) {
                int idx = tid + i * 256;
                int r = idx >> 5, c4 = (idx & 31) << 2;
                float4 v = *(const float4*)(St + r * 132 + c4);
                const float4 bv = *(const float4*)(bb + c4);
                int tok = m0 + half * 64 + r;
                int b = tok >> 13;
                int l = tok & (LP_ - 1);
                float4 res = make_float4(0.f, 0.f, 0.f, 0.f);
                if (l < L_) res = *(const float4*)(X + (size_t)(b * L_ + l) * D_ + n0 + c4);
                v.x += bv.x + res.x;
                v.y += bv.y + res.y;
                v.z += bv.z + res.z;
                v.w += bv.w + res.w;
                *(float4*)(g_y + (size_t)tok * D_ + n0 + c4) = v;
            }
        }
        __syncthreads();
    }
}

// ---------------------------------------------------------------------------
// Register-resident attention (raw mma.sync m16n8k16).
// One CTA = (head, window). 8 warps; warp owns 16 q-rows. S/P/O in registers.
// smem: Q[128][72]h (18432B) | K[128][72]h (18432B) | Vt[64][136]h (17408B)
// Total 54272 B, 2 CTAs/SM. ONE __syncthreads total.
// Softmax: no max-shift; normalization folded into O write (O = (E@V)/rowsum).
// ---------------------------------------------------------------------------
#define QKVS 72
#define VTS  136
#define ATTN_SMEM 54272

__global__ __launch_bounds__(256, 2) void attn_kernel()
{
    __half* Q  = (__half*)dynsm;                      // [128][72]
    __half* K  = Q + 128 * QKVS;                      // [128][72]
    __half* Vt = K + 128 * QKVS;                      // [64][136] transposed V

    const int h = blockIdx.x;
    const int tok0 = blockIdx.y * 128;
    const int tid = threadIdx.x;
    const int wid = tid >> 5;
    const int lane = tid & 31;
    const int wq = wid * 16;                  // warp's q-row base
    const int r = lane >> 2;                  // 0..7
    const int cp = (lane & 3) * 2;            // 0,2,4,6

    // Load Q,K (row-major) and V transposed into Vt
#pragma unroll
    for (int it = 0; it < 4; it++) {
        int idx = tid + it * 256;             // 0..1023
        int row = idx >> 3;
        int c8 = (idx & 7) * 8;
        size_t g = (size_t)(tok0 + row) * D_ + h * HD_ + c8;
        *(uint4*)(Q + row * QKVS + c8) = *(const uint4*)(g_q + g);
        *(uint4*)(K + row * QKVS + c8) = *(const uint4*)(g_k + g);
        uint4 vv = *(const uint4*)(g_v + g);
        __half hv[8];
        *(uint4*)hv = vv;
#pragma unroll
        for (int j = 0; j < 8; j++)
            Vt[(c8 + j) * VTS + row] = hv[j];
    }
    __syncthreads();

    // ---- S = Q @ K^T : 16 n-tiles (8 keys each) x 4 k-steps (d=64) ----
    float sacc[16][4];
#pragma unroll
    for (int t = 0; t < 16; t++)
#pragma unroll
        for (int e = 0; e < 4; e++) sacc[t][e] = 0.0f;

#pragma unroll
    for (int kk = 0; kk < 4; kk++) {
        const int c0 = kk * 16;
        uint32_t a0 = *(uint32_t*)&Q[(wq + r) * QKVS + c0 + cp];
        uint32_t a1 = *(uint32_t*)&Q[(wq + r + 8) * QKVS + c0 + cp];
        uint32_t a2 = *(uint32_t*)&Q[(wq + r) * QKVS + c0 + 8 + cp];
        uint32_t a3 = *(uint32_t*)&Q[(wq + r + 8) * QKVS + c0 + 8 + cp];
#pragma unroll
        for (int nt = 0; nt < 16; nt++) {
            uint32_t b0 = *(uint32_t*)&K[(nt * 8 + r) * QKVS + c0 + cp];
            uint32_t b1 = *(uint32_t*)&K[(nt * 8 + r) * QKVS + c0 + 8 + cp];
            mma16816(sacc[nt], a0, a1, a2, a3, b0, b1);
        }
    }

    // ---- softmax on registers (no shift); pack E to fp16 A-frag format ----
    const float scale = 0.125f;
    float rowA = 0.0f, rowB = 0.0f;           // rows (wq+r) and (wq+r+8)
    uint32_t ph[16][2];
#pragma unroll
    for (int t = 0; t < 16; t++) {
        float e0 = __expf(sacc[t][0] * scale);
        float e1 = __expf(sacc[t][1] * scale);
        float e2 = __expf(sacc[t][2] * scale);
        float e3 = __expf(sacc[t][3] * scale);
        rowA += e0 + e1;
        rowB += e2 + e3;
        __half2 p0 = __floats2half2_rn(e0, e1);
        __half2 p1 = __floats2half2_rn(e2, e3);
        ph[t][0] = *(uint32_t*)&p0;
        ph[t][1] = *(uint32_t*)&p1;
    }
    rowA += __shfl_xor_sync(0xffffffffu, rowA, 1);
    rowA += __shfl_xor_sync(0xffffffffu, rowA, 2);
    rowB += __shfl_xor_sync(0xffffffffu, rowB, 1);
    rowB += __shfl_xor_sync(0xffffffffu, rowB, 2);
    const float invA = 1.0f / rowA;
    const float invB = 1.0f / rowB;

    // ---- O = E @ V : 8 k-steps (128 keys) x 8 n-tiles (d=64) ----
    float oacc[8][4];
#pragma unroll
    for (int t = 0; t < 8; t++)
#pragma unroll
        for (int e = 0; e < 4; e++) oacc[t][e] = 0.0f;

#pragma unroll
    for (int kk = 0; kk < 8; kk++) {
        const int c0 = kk * 16;
        uint32_t a0 = ph[2 * kk][0];
        uint32_t a1 = ph[2 * kk][1];
        uint32_t a2 = ph[2 * kk + 1][0];
        uint32_t a3 = ph[2 * kk + 1][1];
#pragma unroll
        for (int nt = 0; nt < 8; nt++) {
            uint32_t b0 = *(uint32_t*)&Vt[(nt * 8 + r) * VTS + c0 + cp];
            uint32_t b1 = *(uint32_t*)&Vt[(nt * 8 + r) * VTS + c0 + 8 + cp];
            mma16816(oacc[nt], a0, a1, a2, a3, b0, b1);
        }
    }

    // ---- normalize + write O (fp16) direct to gmem ----
    const size_t rowbaseA = (size_t)(tok0 + wq + r) * D_ + h * HD_;
    const size_t rowbaseB = (size_t)(tok0 + wq + r + 8) * D_ + h * HD_;
#pragma unroll
    for (int nt = 0; nt < 8; nt++) {
        __half2 pA = __floats2half2_rn(oacc[nt][0] * invA, oacc[nt][1] * invA);
        __half2 pB = __floats2half2_rn(oacc[nt][2] * invB, oacc[nt][3] * invB);
        *(uint32_t*)(g_o + rowbaseA + nt * 8 + cp) = *(uint32_t*)&pA;
        *(uint32_t*)(g_o + rowbaseB + nt * 8 + cp) = *(uint32_t*)&pB;
    }
}

// ---------------------------------------------------------------------------
// LayerNorm: 192 threads, one float4 per thread.
// ---------------------------------------------------------------------------
__global__ __launch_bounds__(192) void ln_kernel(
    const float* __restrict__ gam, const float* __restrict__ bet,
    float* __restrict__ out)
{
    const int t = blockIdx.x;
    const int b = t / L_;
    const int l = t - b * L_;
    const float4* y = (const float4*)(g_y + (size_t)(b * LP_ + l) * D_);
    const int tid = threadIdx.x;

    float4 v = y[tid];
    float s  = v.x + v.y + v.z + v.w;
    float ss = v.x * v.x + v.y * v.y + v.z * v.z + v.w * v.w;

    __shared__ float red_s[6], red_q[6];
#pragma unroll
    for (int off = 16; off > 0; off >>= 1) {
        s  += __shfl_down_sync(0xffffffffu, s, off);
        ss += __shfl_down_sync(0xffffffffu, ss, off);
    }
    if ((tid & 31) == 0) { red_s[tid >> 5] = s; red_q[tid >> 5] = ss; }
    __syncthreads();
    if (tid < 32) {
        float a = (tid < 6) ? red_s[tid] : 0.0f;
        float q = (tid < 6) ? red_q[tid] : 0.0f;
#pragma unroll
        for (int off = 4; off > 0; off >>= 1) {
            a += __shfl_down_sync(0xffffffffu, a, off);
            q += __shfl_down_sync(0xffffffffu, q, off);
        }
        if (tid == 0) { red_s[0] = a; red_q[0] = q; }
    }
    __syncthreads();

    float mu  = red_s[0] * (1.0f / D_);
    float var = red_q[0] * (1.0f / D_) - mu * mu;
    float inv = rsqrtf(var + 1e-5f);

    float4 g  = ((const float4*)gam)[tid];
    float4 be = ((const float4*)bet)[tid];
    float4 o;
    o.x = (v.x - mu) * inv * g.x + be.x;
    o.y = (v.y - mu) * inv * g.y + be.y;
    o.z = (v.z - mu) * inv * g.z + be.z;
    o.w = (v.w - mu) * inv * g.w + be.w;
    ((float4*)(out + (size_t)t * D_))[tid] = o;
}

// ---------------------------------------------------------------------------
extern "C" void kernel_launch(void* const* d_in, const int* in_sizes, int n_in,
                              void* d_out, int out_size)
{
    const float* x    = (const float*)d_in[0];
    const float* Wq   = (const float*)d_in[1];
    const float* bq   = (const float*)d_in[2];
    const float* Wk   = (const float*)d_in[3];
    const float* bk   = (const float*)d_in[4];
    const float* Wv   = (const float*)d_in[5];
    const float* bv   = (const float*)d_in[6];
    const float* Wo   = (const float*)d_in[7];
    const float* bo   = (const float*)d_in[8];
    const float* ln_g = (const float*)d_in[9];
    const float* ln_b = (const float*)d_in[10];
    float* out = (float*)d_out;

    cudaFuncSetAttribute(gemm_kernel<0>, cudaFuncAttributeMaxDynamicSharedMemorySize, GEMM_SMEM);
    cudaFuncSetAttribute(gemm_kernel<1>, cudaFuncAttributeMaxDynamicSharedMemorySize, GEMM_SMEM);
    cudaFuncSetAttribute(attn_kernel, cudaFuncAttributeMaxDynamicSharedMemorySize, ATTN_SMEM);

    prep_x<<<12288, 256>>>(x);
    prep_wt<<<dim3(24, 24, 4), 256>>>(Wq, Wk, Wv, Wo);
    prep_bias<<<12, 256>>>(bq, bk, bv, bo);
    gemm_kernel<0><<<dim3(NTOK / 128, 18), 256, GEMM_SMEM>>>(nullptr);
    attn_kernel<<<dim3(H_, NTOK / WSZ), 256, ATTN_SMEM>>>();
    gemm_kernel<1><<<dim3(NTOK / 128, 6), 256, GEMM_SMEM>>>(x);
    ln_kernel<<<B_ * L_, 192>>>(ln_g, ln_b, out);
}